// round 2
// baseline (speedup 1.0000x reference)
#include <cuda_runtime.h>

#define BB   64
#define HH   384
#define NPLT 16
#define NG   25
#define CAND 625   // NG*NG
#define LF   400   // HH + NPLT

#define LOG2E_F  1.4426950408889634f
#define LOG2PI_F 1.8378770664093453f

// persistent scratch (allocation-free rule: __device__ globals)
__device__ float g_xlim[NG];
__device__ float g_ylim[NG];
__device__ float g_S[BB * CAND];
__device__ float g_pred[BB * NPLT * 2];
__device__ float g_c2;    // (0.5/sigma^2) * LOG2E
__device__ float g_beta;

__device__ __forceinline__ float ex2f(float x) {
    float r;
    asm("ex2.approx.ftz.f32 %0, %1;" : "=f"(r) : "f"(x));
    return r;
}

// ---------------------------------------------------------------------------
// Kernel 1: grid bounds from history points 0 and 1 (across all batches+dims),
// linspace grids, and scalar constants.
// ---------------------------------------------------------------------------
__global__ void k_setup(const float* __restrict__ hist,
                        const float* __restrict__ beta_p,
                        const float* __restrict__ logsig_p) {
    __shared__ float sm[128];
    __shared__ float bounds[4];  // minx, maxx, miny, maxy
    int t = threadIdx.x;         // 128 threads
    int b = t >> 1, d = t & 1;
    float v0 = hist[b * (HH * 2) + d];      // point 0 of batch b, dim d
    float v1 = hist[b * (HH * 2) + 2 + d];  // point 1

    // minx
    sm[t] = v0; __syncthreads();
    for (int o = 64; o; o >>= 1) { if (t < o) sm[t] = fminf(sm[t], sm[t + o]); __syncthreads(); }
    if (t == 0) bounds[0] = sm[0];
    __syncthreads();
    // maxx
    sm[t] = v0; __syncthreads();
    for (int o = 64; o; o >>= 1) { if (t < o) sm[t] = fmaxf(sm[t], sm[t + o]); __syncthreads(); }
    if (t == 0) bounds[1] = sm[0];
    __syncthreads();
    // miny
    sm[t] = v1; __syncthreads();
    for (int o = 64; o; o >>= 1) { if (t < o) sm[t] = fminf(sm[t], sm[t + o]); __syncthreads(); }
    if (t == 0) bounds[2] = sm[0];
    __syncthreads();
    // maxy
    sm[t] = v1; __syncthreads();
    for (int o = 64; o; o >>= 1) { if (t < o) sm[t] = fmaxf(sm[t], sm[t + o]); __syncthreads(); }
    if (t == 0) bounds[3] = sm[0];
    __syncthreads();

    if (t == 0) {
        float sig = expf(logsig_p[0]);
        g_c2 = (0.5f / (sig * sig)) * LOG2E_F;
        g_beta = beta_p[0];
    }
    if (t < NG) {
        float minx = bounds[0], maxx = bounds[1];
        float miny = bounds[2], maxy = bounds[3];
        g_xlim[t] = (t == NG - 1) ? maxx : minx + (maxx - minx) * ((float)t / (float)(NG - 1));
        g_ylim[t] = (t == NG - 1) ? maxy : miny + (maxy - miny) * ((float)t / (float)(NG - 1));
    }
}

// ---------------------------------------------------------------------------
// Kernel 2: base S[b][k] = sum_{j<384} exp(beta*t_j - c*||p_k - h_j||^2)
// grid (5 chunks, 64 batches), 128 threads; 125 candidates per chunk.
// ---------------------------------------------------------------------------
__global__ void k_base(const float* __restrict__ itime,
                       const float* __restrict__ hist) {
    __shared__ float sx[HH], sy[HH], sbt[HH];
    int b = blockIdx.y;
    int t = threadIdx.x;
    float beta = g_beta, c2 = g_c2;

    for (int j = t; j < HH; j += 128) {
        sx[j]  = hist[b * (HH * 2) + 2 * j];
        sy[j]  = hist[b * (HH * 2) + 2 * j + 1];
        sbt[j] = beta * itime[b * HH + j] * LOG2E_F;
    }
    __syncthreads();

    if (t < 125) {
        int k = blockIdx.x * 125 + t;
        float cx = g_xlim[k % NG];
        float cy = g_ylim[k / NG];
        float s = 0.f;
#pragma unroll 4
        for (int j = 0; j < HH; j++) {
            float dx = cx - sx[j];
            float dy = cy - sy[j];
            float sq = fmaf(dx, dx, dy * dy);
            s += ex2f(fmaf(-c2, sq, sbt[j]));
        }
        g_S[b * CAND + k] = s;
    }
}

// ---------------------------------------------------------------------------
// Kernel 3: the 16-step sequential prediction loop, fused into one kernel.
// One block per batch, 640 threads (1 candidate/thread).
// argmin(ll) == argmin(S); tie-break by smallest index (matches jnp.argmin)
// via packed (float_bits(S) << 32 | idx) min-reduction (S >= 0 so bits are
// order-preserving).
// ---------------------------------------------------------------------------
__global__ void k_iter(const float* __restrict__ curr,
                       float* __restrict__ out) {
    __shared__ unsigned long long wred[32];
    __shared__ unsigned long long sbest;
    int b = blockIdx.x;
    int t = threadIdx.x;          // 640 threads, 20 warps
    bool act = (t < CAND);

    float cx = 0.f, cy = 0.f, s = 0.f;
    if (act) {
        cx = g_xlim[t % NG];
        cy = g_ylim[t / NG];
        s  = g_S[b * CAND + t];
    }
    float c2 = g_c2, beta = g_beta;

    for (int i = 0; i < NPLT; i++) {
        unsigned long long key = act
            ? ((((unsigned long long)__float_as_uint(s)) << 32) | (unsigned)t)
            : 0xFFFFFFFFFFFFFFFFULL;
        // warp min
        for (int o = 16; o; o >>= 1) {
            unsigned long long other = __shfl_down_sync(0xffffffffu, key, o);
            key = (other < key) ? other : key;
        }
        if ((t & 31) == 0) wred[t >> 5] = key;
        __syncthreads();
        if (t < 32) {
            unsigned long long kk = (t < 20) ? wred[t] : 0xFFFFFFFFFFFFFFFFULL;
            for (int o = 16; o; o >>= 1) {
                unsigned long long other = __shfl_down_sync(0xffffffffu, kk, o);
                kk = (other < kk) ? other : kk;
            }
            if (t == 0) sbest = kk;
        }
        __syncthreads();

        unsigned idx = (unsigned)(sbest & 0xffffffffu);
        float px = g_xlim[idx % NG];
        float py = g_ylim[idx / NG];

        if (t == 0) {
            out[BB + (i * BB + b) * 2 + 0] = px;
            out[BB + (i * BB + b) * 2 + 1] = py;
            g_pred[(b * NPLT + i) * 2 + 0] = px;
            g_pred[(b * NPLT + i) * 2 + 1] = py;
        }
        if (act && i < NPLT - 1) {
            float dx = cx - px;
            float dy = cy - py;
            float sq = fmaf(dx, dx, dy * dy);
            float bt = beta * curr[b * NPLT + i] * LOG2E_F;
            s += ex2f(fmaf(-c2, sq, bt));
        }
        // wred reuse is ordered by the sync at the top of the next iteration
    }
}

// ---------------------------------------------------------------------------
// Kernel 4: final GMM log-likelihood over L=400 points per batch.
// logp_i = log(S2_i) - log(S1_i) - C, with
//   S1_i = sum_{j<i} exp(-beta*dt), S2_i = sum_{j<i} exp(-beta*dt - c*sq),
//   C = 2*log(sigma) + log(2*pi).
// One block per batch, 512 threads, one warp per row.
// ---------------------------------------------------------------------------
__global__ void k_gmm(const float* __restrict__ itime,
                      const float* __restrict__ hist,
                      const float* __restrict__ curr,
                      const float* __restrict__ logsig_p,
                      float* __restrict__ out) {
    __shared__ float px[LF], py[LF], pt[LF];
    __shared__ float warpacc[16];
    int b = blockIdx.x;
    int t = threadIdx.x;  // 512

    for (int j = t; j < HH; j += 512) {
        px[j] = hist[b * (HH * 2) + 2 * j];
        py[j] = hist[b * (HH * 2) + 2 * j + 1];
        pt[j] = itime[b * HH + j];
    }
    if (t < NPLT) {
        px[HH + t] = g_pred[(b * NPLT + t) * 2 + 0];
        py[HH + t] = g_pred[(b * NPLT + t) * 2 + 1];
        pt[HH + t] = curr[b * NPLT + t];
    }
    __syncthreads();

    float beta = g_beta, c2 = g_c2;
    int w = t >> 5, lane = t & 31;
    float acc = 0.f;

    for (int i = 1 + w; i < LF; i += 16) {
        float ti = pt[i], xi = px[i], yi = py[i];
        float s1 = 0.f, s2 = 0.f;
        for (int j = lane; j < i; j += 32) {
            float a2 = (pt[j] - ti) * beta * LOG2E_F;  // -beta*dt in log2 units
            float dx = xi - px[j];
            float dy = yi - py[j];
            float sq = fmaf(dx, dx, dy * dy);
            s1 += ex2f(a2);
            s2 += ex2f(fmaf(-c2, sq, a2));
        }
        for (int o = 16; o; o >>= 1) {
            s1 += __shfl_down_sync(0xffffffffu, s1, o);
            s2 += __shfl_down_sync(0xffffffffu, s2, o);
        }
        if (lane == 0) acc += logf(s2) - logf(s1);
    }
    if (lane == 0) warpacc[w] = acc;
    __syncthreads();

    if (t == 0) {
        float tot = 0.f;
        for (int w2 = 0; w2 < 16; w2++) tot += warpacc[w2];
        float ls = logsig_p[0];
        float C = 2.f * ls + LOG2PI_F;
        float x0 = px[0], y0 = py[0];
        float logp0 = -0.5f * (x0 * x0 + y0 * y0) - LOG2PI_F;
        out[b] = logp0 + tot - (float)(LF - 1) * C;
    }
}

// ---------------------------------------------------------------------------
extern "C" void kernel_launch(void* const* d_in, const int* in_sizes, int n_in,
                              void* d_out, int out_size) {
    const float* curr   = (const float*)d_in[0];  // (64,16)
    const float* itime  = (const float*)d_in[1];  // (64,384)
    const float* hist   = (const float*)d_in[2];  // (64,384,2)
    // d_in[3..5] (expected_data, aux_*) are dead inputs
    const float* beta   = (const float*)d_in[6];
    const float* logsig = (const float*)d_in[7];
    float* out = (float*)d_out;  // [64 loglik][16*64*2 predicted]

    k_setup<<<1, 128>>>(hist, beta, logsig);
    k_base<<<dim3(5, BB), 128>>>(itime, hist);
    k_iter<<<BB, 640>>>(curr, out);
    k_gmm<<<BB, 512>>>(itime, hist, curr, logsig, out);
}